// round 15
// baseline (speedup 1.0000x reference)
#include <cuda_runtime.h>
#include <math.h>

#define NMATS 200
#define BATCH 64
#define DIM 64
#define TOTAL (NMATS * BATCH)      // 12800
#define MATELEMS (DIM * DIM)       // 4096
#define LDU 66                     // even padded stride: aligned LDS.64, conflict-free
#define NSWEEPS 8
#define FULLMASK 0xffffffffu

__device__ float g_logm[(size_t)TOTAL * MATELEMS];
__device__ float g_mean[BATCH * MATELEMS];

// ---- packed f32x2 helpers (Blackwell) -------------------------------------
typedef unsigned long long u64;
__device__ __forceinline__ u64 pk(float lo, float hi) {
    u64 r; asm("mov.b64 %0,{%1,%2};" : "=l"(r) : "f"(lo), "f"(hi)); return r;
}
__device__ __forceinline__ void upk(u64 v, float& lo, float& hi) {
    asm("mov.b64 {%0,%1},%2;" : "=f"(lo), "=f"(hi) : "l"(v));
}
__device__ __forceinline__ u64 fma2(u64 a, u64 b, u64 c) {
    u64 d; asm("fma.rn.f32x2 %0,%1,%2,%3;" : "=l"(d) : "l"(a), "l"(b), "l"(c)); return d;
}
__device__ __forceinline__ u64 mul2(u64 a, u64 b) {
    u64 d; asm("mul.rn.f32x2 %0,%1,%2;" : "=l"(d) : "l"(a), "l"(b)); return d;
}
__device__ __forceinline__ float hsum2(u64 v0, u64 v1) {
    float x0, y0, x1, y1;
    upk(v0, x0, y0); upk(v1, x1, y1);
    return (x0 + y0) + (x1 + y1);
}

// ---------------------------------------------------------------------------
// Stage 1: register-resident one-sided Jacobi, recursive-bisection schedule,
// branchless deferred-cosine rotations, incremental norms, packed f32x2 math.
// TWO warps per matrix (row-split): lane t of warp w owns rows [32w,32w+32)
// of columns (2t, 2t+1), stored as 16 packed row-pairs per column.
// The NEXT round's cross dot is fused into the rotate/shuffle loop, removing
// the exposed dot-chain latency between rotate and the reduction barrier.
// NO launch_bounds: natural allocation is the only spill-free point
// (any reg cap makes ptxas spill the column arrays — verified R7/R8/R13).
// ---------------------------------------------------------------------------
__global__ void jacobi_log_kernel(const float* __restrict__ X)
{
    __shared__ __align__(16) float U[DIM * LDU];   // reconstruction
    __shared__ float gcoef[DIM];
    __shared__ float red[2][64];        // cross-warp reduce (round parity)

    const int tid  = threadIdx.x;       // 0..63
    const int lane = tid & 31;
    const int w    = tid >> 5;          // row-half
    const size_t mat = blockIdx.x;
    const float* Xm = X + mat * (size_t)MATELEMS;

    // Load owned half-columns; repack AoS (a,b) pairs -> row-pair packing.
    u64 A[16], B[16];
    {
        const u64* X8 = (const u64*)Xm;   // {col 2lane, col 2lane+1} per row
        #pragma unroll
        for (int j = 0; j < 16; ++j) {
            u64 v0 = X8[(size_t)(32 * w + 2 * j)     * 32 + lane];
            u64 v1 = X8[(size_t)(32 * w + 2 * j + 1) * 32 + lane];
            float a0, b0, a1, b1;
            upk(v0, a0, b0); upk(v1, a1, b1);
            A[j] = pk(a0, a1); B[j] = pk(b0, b1);
        }
    }

    // Initial norms: packed partial per half, reduce across warps.
    float na, nb;
    {
        u64 p2 = 0ull, p3 = 0ull, q2 = 0ull, q3 = 0ull;
        #pragma unroll
        for (int j = 0; j < 16; j += 2) {
            p2 = fma2(A[j], A[j], p2);     p3 = fma2(A[j+1], A[j+1], p3);
            q2 = fma2(B[j], B[j], q2);     q3 = fma2(B[j+1], B[j+1], q3);
        }
        float pna = hsum2(p2, p3);
        float pnb = hsum2(q2, q3);
        red[0][tid] = pna;
        red[1][tid] = pnb;
        __syncthreads();
        na = pna + red[0][lane + 32 * (1 - w)];
        nb = pnb + red[1][lane + 32 * (1 - w)];
        __syncthreads();
    }
    float sa = 1.f, sb = 1.f, isa = 1.f, isb = 1.f;

    const int other = lane + 32 * (1 - w);
    int par = 0;

    for (int sweep = 0; sweep < NSWEEPS; ++sweep) {
        int g = 32;                      // lanes per group (2g columns/group)
        #pragma unroll
        for (int level = 0; level < 6; ++level) {
            const int gm1 = g - 1;
            const int rot_src = (lane & ~gm1) | ((lane + 1) & gm1);

            // Explicit dot at level entry (invalidated by redistribution).
            float pd;
            {
                u64 e0 = 0ull, e1 = 0ull;
                #pragma unroll
                for (int j = 0; j < 16; j += 2) {
                    e0 = fma2(A[j],     B[j],     e0);
                    e1 = fma2(A[j + 1], B[j + 1], e1);
                }
                pd = hsum2(e0, e1);
            }

            for (int r = 0; r < g; ++r) {
                // Cross-warp reduce (bit-identical in both warps).
                red[par][tid] = pd;
                __syncthreads();
                float s01 = pd + red[par][other];
                par ^= 1;

                float a01 = s01 * sa * sb;                // true off-diagonal

                // Branchless rotation, single-division tangent:
                // t = -2*a01 / copysign(|d| + sqrt(d^2 + 4*a01^2), d)
                float d = na - nb;
                float a01sq = a01 * a01;
                bool act = a01sq > (1e-14f * (na * nb));
                float w2 = sqrtf(fmaf(d, d, 4.f * a01sq));
                float tt = __fdividef(-2.f * a01,
                                      copysignf(fabsf(d) + w2, d));
                tt = act ? tt : 0.f;
                float opt2 = fmaf(tt, tt, 1.f);
                float c = rsqrtf(opt2);                   // 1 when tt=0
                float h = opt2 * c;                       // = 1/c
                float t1 = tt * sb * isa;                 // t*sb/sa (no div)
                float t2 = tt * sa * isb;                 // t*sa/sb (no div)
                na = fmaf(-tt, a01, na);                  // a00' = a00 - t*a01
                nb = fmaf( tt, a01, nb);                  // a11' = a11 + t*a01
                sa *= c; sb *= c; isa *= h; isb *= h;     // deferred cosine

                // Fused packed rotate + ring-rotate of b + NEXT round's dot.
                u64 t1p = pk(-t1, -t1), t2p = pk(t2, t2);
                u64 f0 = 0ull, f1 = 0ull;
                #pragma unroll
                for (int j = 0; j < 16; ++j) {
                    u64 x = A[j], y = B[j];
                    u64 xn = fma2(t1p, y, x);
                    u64 yn = fma2(t2p, x, y);
                    A[j] = xn;
                    float lo, hi;
                    upk(yn, lo, hi);
                    lo = __shfl_sync(FULLMASK, lo, rot_src);
                    hi = __shfl_sync(FULLMASK, hi, rot_src);
                    u64 bn = pk(lo, hi);
                    B[j] = bn;
                    if (j & 1) f1 = fma2(xn, bn, f1);
                    else       f0 = fma2(xn, bn, f0);
                }
                nb  = __shfl_sync(FULLMASK, nb,  rot_src);
                sb  = __shfl_sync(FULLMASK, sb,  rot_src);
                isb = __shfl_sync(FULLMASK, isb, rot_src);
                pd = hsum2(f0, f1);       // dot for next round (waste on last)
            }

            // Redistribute: low half-lanes collect the a-set, high half b-set.
            if (g > 1) {
                const int half = g >> 1;
                const bool low = (lane & gm1) < half;
                const int partner = low ? (lane + half) : (lane - half);
                #pragma unroll
                for (int j = 0; j < 16; ++j) {
                    u64 send = low ? B[j] : A[j];
                    float lo, hi;
                    upk(send, lo, hi);
                    lo = __shfl_sync(FULLMASK, lo, partner);
                    hi = __shfl_sync(FULLMASK, hi, partner);
                    u64 recv = pk(lo, hi);
                    if (low) B[j] = recv; else A[j] = recv;
                }
                float sn = low ? nb : na;
                float rn = __shfl_sync(FULLMASK, sn, partner);
                if (low) nb = rn; else na = rn;
                float ss = low ? sb : sa;
                float rs = __shfl_sync(FULLMASK, ss, partner);
                if (low) sb = rs; else sa = rs;
                float si = low ? isb : isa;
                float ri = __shfl_sync(FULLMASK, si, partner);
                if (low) isb = ri; else isa = ri;
            }
            g >>= 1;
        }

        // Renormalize stored columns once per sweep (packed).
        {
            u64 sap = pk(sa, sa), sbp = pk(sb, sb);
            #pragma unroll
            for (int j = 0; j < 16; ++j) {
                A[j] = mul2(A[j], sap);
                B[j] = mul2(B[j], sbp);
            }
        }
        sa = 1.f; sb = 1.f; isa = 1.f; isb = 1.f;
    }

    // Stash converged half-columns (aligned u64 stores).
    #pragma unroll
    for (int j = 0; j < 16; ++j) {
        *(u64*)&U[(2 * lane)     * LDU + 32 * w + 2 * j] = A[j];
        *(u64*)&U[(2 * lane + 1) * LDU + 32 * w + 2 * j] = B[j];
    }
    // Exact final norms -> spectral coefficients.
    {
        u64 p2 = 0ull, p3 = 0ull, q2 = 0ull, q3 = 0ull;
        #pragma unroll
        for (int j = 0; j < 16; j += 2) {
            p2 = fma2(A[j], A[j], p2);     p3 = fma2(A[j+1], A[j+1], p3);
            q2 = fma2(B[j], B[j], q2);     q3 = fma2(B[j+1], B[j+1], q3);
        }
        float pna = hsum2(p2, p3);
        float pnb = hsum2(q2, q3);
        red[0][tid] = pna;
        red[1][tid] = pnb;
        __syncthreads();
        if (w == 0) {
            float nna = pna + red[0][other];   // lambda^2
            float nnb = pnb + red[1][other];
            gcoef[2 * lane]     = 0.5f * logf(nna) / nna;
            gcoef[2 * lane + 1] = 0.5f * logf(nnb) / nnb;
        }
    }
    __syncthreads();

    // logm = sum_j g_j u_j u_j^T; thread handles row m = tid. Packed fma2.
    float* outm = g_logm + mat * (size_t)MATELEMS;
    const int m = tid;
    for (int h2 = 0; h2 < 2; ++h2) {
        u64 acc2[16];
        #pragma unroll
        for (int n = 0; n < 16; ++n) acc2[n] = 0ull;
        for (int j = 0; j < DIM; ++j) {
            float aj = gcoef[j] * U[j * LDU + m];
            u64 ajp = pk(aj, aj);
            const u64* uj2 = (const u64*)&U[j * LDU + h2 * 32];
            #pragma unroll
            for (int n = 0; n < 16; ++n) acc2[n] = fma2(ajp, uj2[n], acc2[n]);
        }
        #pragma unroll
        for (int n = 0; n < 16; ++n) {
            float lo, hi;
            upk(acc2[n], lo, hi);
            outm[(size_t)(h2 * 32 + 2 * n)     * DIM + m] = lo;
            outm[(size_t)(h2 * 32 + 2 * n + 1) * DIM + m] = hi;
        }
    }
}

// ---------------------------------------------------------------------------
// Stage 2: mean over N.
// ---------------------------------------------------------------------------
__global__ void mean_kernel()
{
    int idx = blockIdx.x * blockDim.x + threadIdx.x;
    if (idx >= BATCH * MATELEMS) return;
    const float* p = g_logm + idx;
    float s = 0.f;
    #pragma unroll 4
    for (int i = 0; i < NMATS; ++i)
        s += p[(size_t)i * (BATCH * MATELEMS)];
    g_mean[idx] = s * (1.f / NMATS);
}

// ---------------------------------------------------------------------------
// Stage 3: expm via scaling-and-squaring Taylor (E = mean/16, degree-8
// Horner, 4 squarings). One 256-thread block per batch entry. Packed fma2.
// ---------------------------------------------------------------------------
__device__ __forceinline__ void mm_acc2(u64* __restrict__ acc2,
                                        const float* __restrict__ A,
                                        const float* __restrict__ Bm,
                                        int m, int nb)
{
    #pragma unroll
    for (int n = 0; n < 8; ++n) acc2[n] = 0ull;
    for (int j = 0; j < DIM; ++j) {
        float av = A[m * LDU + j];
        u64 avp = pk(av, av);
        const u64* brow = (const u64*)&Bm[j * LDU + nb];
        #pragma unroll
        for (int n = 0; n < 8; ++n) acc2[n] = fma2(avp, brow[n], acc2[n]);
    }
}

__global__ __launch_bounds__(256) void expm_kernel(float* __restrict__ out)
{
    __shared__ __align__(16) float E[DIM * LDU];
    __shared__ __align__(16) float P[DIM * LDU];
    const int b = blockIdx.x;
    const int tid = threadIdx.x;
    const int m  = tid >> 2;
    const int nb = (tid & 3) << 4;    // 0,16,32,48 — even, u64-aligned

    for (int idx = tid; idx < MATELEMS; idx += 256) {
        int r = idx >> 6, c = idx & 63;
        float e = g_mean[b * MATELEMS + idx] * (1.f / 16.f);
        E[r * LDU + c] = e;
        P[r * LDU + c] = e * 0.125f + (r == c ? 1.f : 0.f);
    }
    __syncthreads();

    for (int k = 7; k >= 1; --k) {
        u64 acc2[8];
        mm_acc2(acc2, E, P, m, nb);
        __syncthreads();
        float inv = 1.f / (float)k;
        #pragma unroll
        for (int n = 0; n < 8; ++n) {
            float lo, hi;
            upk(acc2[n], lo, hi);
            int c0 = nb + 2 * n;
            P[m * LDU + c0]     = lo * inv + ((m == c0)     ? 1.f : 0.f);
            P[m * LDU + c0 + 1] = hi * inv + ((m == c0 + 1) ? 1.f : 0.f);
        }
        __syncthreads();
    }

    for (int sq = 0; sq < 4; ++sq) {
        u64 acc2[8];
        mm_acc2(acc2, P, P, m, nb);
        __syncthreads();
        #pragma unroll
        for (int n = 0; n < 8; ++n) {
            float lo, hi;
            upk(acc2[n], lo, hi);
            P[m * LDU + nb + 2 * n]     = lo;
            P[m * LDU + nb + 2 * n + 1] = hi;
        }
        __syncthreads();
    }

    for (int idx = tid; idx < MATELEMS; idx += 256) {
        int r = idx >> 6, c = idx & 63;
        out[(size_t)b * MATELEMS + idx] = P[r * LDU + c];
    }
}

// ---------------------------------------------------------------------------
extern "C" void kernel_launch(void* const* d_in, const int* in_sizes, int n_in,
                              void* d_out, int out_size)
{
    (void)in_sizes; (void)n_in; (void)out_size;
    const float* X = (const float*)d_in[0];
    float* out = (float*)d_out;

    jacobi_log_kernel<<<TOTAL, 64>>>(X);
    mean_kernel<<<(BATCH * MATELEMS + 255) / 256, 256>>>();
    expm_kernel<<<BATCH, 256>>>(out);
}

// round 16
// speedup vs baseline: 1.0568x; 1.0568x over previous
#include <cuda_runtime.h>
#include <math.h>

#define NMATS 200
#define BATCH 64
#define DIM 64
#define TOTAL (NMATS * BATCH)      // 12800
#define MATELEMS (DIM * DIM)       // 4096
#define LDU 66                     // even padded stride: aligned LDS.64, conflict-free
#define NSWEEPS 8
#define FULLMASK 0xffffffffu

__device__ float g_logm[(size_t)TOTAL * MATELEMS];
__device__ float g_mean[BATCH * MATELEMS];

// ---- packed f32x2 helpers (Blackwell) -------------------------------------
typedef unsigned long long u64;
__device__ __forceinline__ u64 pk(float lo, float hi) {
    u64 r; asm("mov.b64 %0,{%1,%2};" : "=l"(r) : "f"(lo), "f"(hi)); return r;
}
__device__ __forceinline__ void upk(u64 v, float& lo, float& hi) {
    asm("mov.b64 {%0,%1},%2;" : "=f"(lo), "=f"(hi) : "l"(v));
}
__device__ __forceinline__ u64 fma2(u64 a, u64 b, u64 c) {
    u64 d; asm("fma.rn.f32x2 %0,%1,%2,%3;" : "=l"(d) : "l"(a), "l"(b), "l"(c)); return d;
}
__device__ __forceinline__ u64 mul2(u64 a, u64 b) {
    u64 d; asm("mul.rn.f32x2 %0,%1,%2;" : "=l"(d) : "l"(a), "l"(b)); return d;
}
__device__ __forceinline__ u64 add2(u64 a, u64 b) {
    u64 d; asm("add.rn.f32x2 %0,%1,%2;" : "=l"(d) : "l"(a), "l"(b)); return d;
}
// Horizontal sum of two packed accumulators: 1 packed add + 1 scalar add.
__device__ __forceinline__ float hsum2(u64 v0, u64 v1) {
    u64 s = add2(v0, v1);
    float lo, hi; upk(s, lo, hi);
    return lo + hi;
}

// ---------------------------------------------------------------------------
// Stage 1: register-resident one-sided Jacobi, recursive-bisection schedule,
// branchless deferred-cosine rotations, incremental norms, packed f32x2 math.
// TWO warps per matrix (row-split): lane t of warp w owns rows [32w,32w+32)
// of columns (2t, 2t+1), stored as 16 packed row-pairs per column.
// Cross-warp dot reduction: parity-alternated smem + 1 barrier/round; the
// reduced value is bit-identical in both warps, so scalar state replicates.
// Native u64 shuffles (no explicit pack/unpack movs around SHFL).
// NO launch_bounds: natural allocation is the only spill-free point
// (any reg cap makes ptxas spill the column arrays — verified R7/R8/R13).
// ---------------------------------------------------------------------------
__global__ void jacobi_log_kernel(const float* __restrict__ X)
{
    __shared__ __align__(16) float U[DIM * LDU];   // reconstruction
    __shared__ float gcoef[DIM];
    __shared__ float red[2][64];        // cross-warp reduce (round parity)

    const int tid  = threadIdx.x;       // 0..63
    const int lane = tid & 31;
    const int w    = tid >> 5;          // row-half
    const size_t mat = blockIdx.x;
    const float* Xm = X + mat * (size_t)MATELEMS;

    // Load owned half-columns; repack AoS (a,b) pairs -> row-pair packing.
    u64 A[16], B[16];
    {
        const u64* X8 = (const u64*)Xm;   // {col 2lane, col 2lane+1} per row
        #pragma unroll
        for (int j = 0; j < 16; ++j) {
            u64 v0 = X8[(size_t)(32 * w + 2 * j)     * 32 + lane];
            u64 v1 = X8[(size_t)(32 * w + 2 * j + 1) * 32 + lane];
            float a0, b0, a1, b1;
            upk(v0, a0, b0); upk(v1, a1, b1);
            A[j] = pk(a0, a1); B[j] = pk(b0, b1);
        }
    }

    // Initial norms: packed partial per half, reduce across warps.
    float na, nb;
    {
        u64 p2 = 0ull, p3 = 0ull, q2 = 0ull, q3 = 0ull;
        #pragma unroll
        for (int j = 0; j < 16; j += 2) {
            p2 = fma2(A[j], A[j], p2);     p3 = fma2(A[j+1], A[j+1], p3);
            q2 = fma2(B[j], B[j], q2);     q3 = fma2(B[j+1], B[j+1], q3);
        }
        float pna = hsum2(p2, p3);
        float pnb = hsum2(q2, q3);
        red[0][tid] = pna;
        red[1][tid] = pnb;
        __syncthreads();
        na = pna + red[0][lane + 32 * (1 - w)];
        nb = pnb + red[1][lane + 32 * (1 - w)];
        __syncthreads();
    }
    float sa = 1.f, sb = 1.f, isa = 1.f, isb = 1.f;

    const int other = lane + 32 * (1 - w);
    int par = 0;

    for (int sweep = 0; sweep < NSWEEPS; ++sweep) {
        int g = 32;                      // lanes per group (2g columns/group)
        #pragma unroll
        for (int level = 0; level < 6; ++level) {
            const int gm1 = g - 1;
            const int rot_src = (lane & ~gm1) | ((lane + 1) & gm1);

            for (int r = 0; r < g; ++r) {
                // Packed partial cross dot (own row half), 2 chains.
                u64 d0 = 0ull, d1 = 0ull;
                #pragma unroll
                for (int j = 0; j < 16; j += 2) {
                    d0 = fma2(A[j],     B[j],     d0);
                    d1 = fma2(A[j + 1], B[j + 1], d1);
                }
                float pd = hsum2(d0, d1);

                // Cross-warp reduce (bit-identical in both warps).
                red[par][tid] = pd;
                __syncthreads();
                float s01 = pd + red[par][other];
                par ^= 1;

                float a01 = s01 * sa * sb;                // true off-diagonal

                // Branchless rotation, single-division tangent:
                // t = -2*a01 / copysign(|d| + sqrt(d^2 + 4*a01^2), d)
                float d = na - nb;
                float a01sq = a01 * a01;
                bool act = a01sq > (1e-14f * (na * nb));
                float w2 = sqrtf(fmaf(d, d, 4.f * a01sq));
                float tt = __fdividef(-2.f * a01,
                                      copysignf(fabsf(d) + w2, d));
                tt = act ? tt : 0.f;
                float opt2 = fmaf(tt, tt, 1.f);
                float c = rsqrtf(opt2);                   // 1 when tt=0
                float h = opt2 * c;                       // = 1/c
                float t1 = tt * sb * isa;                 // t*sb/sa (no div)
                float t2 = tt * sa * isb;                 // t*sa/sb (no div)
                na = fmaf(-tt, a01, na);                  // a00' = a00 - t*a01
                nb = fmaf( tt, a01, nb);                  // a11' = a11 + t*a01
                sa *= c; sb *= c; isa *= h; isb *= h;     // deferred cosine

                // Fused packed rotate + ring-rotate of b (native u64 shfl).
                u64 t1p = pk(-t1, -t1), t2p = pk(t2, t2);
                #pragma unroll
                for (int j = 0; j < 16; ++j) {
                    u64 x = A[j], y = B[j];
                    u64 xn = fma2(t1p, y, x);
                    u64 yn = fma2(t2p, x, y);
                    A[j] = xn;
                    B[j] = __shfl_sync(FULLMASK, yn, rot_src);
                }
                nb  = __shfl_sync(FULLMASK, nb,  rot_src);
                sb  = __shfl_sync(FULLMASK, sb,  rot_src);
                isb = __shfl_sync(FULLMASK, isb, rot_src);
            }

            // Redistribute: low half-lanes collect the a-set, high half b-set.
            if (g > 1) {
                const int half = g >> 1;
                const bool low = (lane & gm1) < half;
                const int partner = low ? (lane + half) : (lane - half);
                #pragma unroll
                for (int j = 0; j < 16; ++j) {
                    u64 send = low ? B[j] : A[j];
                    u64 recv = __shfl_sync(FULLMASK, send, partner);
                    if (low) B[j] = recv; else A[j] = recv;
                }
                float sn = low ? nb : na;
                float rn = __shfl_sync(FULLMASK, sn, partner);
                if (low) nb = rn; else na = rn;
                float ss = low ? sb : sa;
                float rs = __shfl_sync(FULLMASK, ss, partner);
                if (low) sb = rs; else sa = rs;
                float si = low ? isb : isa;
                float ri = __shfl_sync(FULLMASK, si, partner);
                if (low) isb = ri; else isa = ri;
            }
            g >>= 1;
        }

        // Renormalize stored columns once per sweep (packed).
        {
            u64 sap = pk(sa, sa), sbp = pk(sb, sb);
            #pragma unroll
            for (int j = 0; j < 16; ++j) {
                A[j] = mul2(A[j], sap);
                B[j] = mul2(B[j], sbp);
            }
        }
        sa = 1.f; sb = 1.f; isa = 1.f; isb = 1.f;
    }

    // Stash converged half-columns (aligned u64 stores).
    #pragma unroll
    for (int j = 0; j < 16; ++j) {
        *(u64*)&U[(2 * lane)     * LDU + 32 * w + 2 * j] = A[j];
        *(u64*)&U[(2 * lane + 1) * LDU + 32 * w + 2 * j] = B[j];
    }
    // Exact final norms -> spectral coefficients.
    {
        u64 p2 = 0ull, p3 = 0ull, q2 = 0ull, q3 = 0ull;
        #pragma unroll
        for (int j = 0; j < 16; j += 2) {
            p2 = fma2(A[j], A[j], p2);     p3 = fma2(A[j+1], A[j+1], p3);
            q2 = fma2(B[j], B[j], q2);     q3 = fma2(B[j+1], B[j+1], q3);
        }
        float pna = hsum2(p2, p3);
        float pnb = hsum2(q2, q3);
        red[0][tid] = pna;
        red[1][tid] = pnb;
        __syncthreads();
        if (w == 0) {
            float nna = pna + red[0][other];   // lambda^2
            float nnb = pnb + red[1][other];
            gcoef[2 * lane]     = 0.5f * logf(nna) / nna;
            gcoef[2 * lane + 1] = 0.5f * logf(nnb) / nnb;
        }
    }
    __syncthreads();

    // logm = sum_j g_j u_j u_j^T; thread handles row m = tid. Packed fma2.
    float* outm = g_logm + mat * (size_t)MATELEMS;
    const int m = tid;
    for (int h2 = 0; h2 < 2; ++h2) {
        u64 acc2[16];
        #pragma unroll
        for (int n = 0; n < 16; ++n) acc2[n] = 0ull;
        for (int j = 0; j < DIM; ++j) {
            float aj = gcoef[j] * U[j * LDU + m];
            u64 ajp = pk(aj, aj);
            const u64* uj2 = (const u64*)&U[j * LDU + h2 * 32];
            #pragma unroll
            for (int n = 0; n < 16; ++n) acc2[n] = fma2(ajp, uj2[n], acc2[n]);
        }
        #pragma unroll
        for (int n = 0; n < 16; ++n) {
            float lo, hi;
            upk(acc2[n], lo, hi);
            outm[(size_t)(h2 * 32 + 2 * n)     * DIM + m] = lo;
            outm[(size_t)(h2 * 32 + 2 * n + 1) * DIM + m] = hi;
        }
    }
}

// ---------------------------------------------------------------------------
// Stage 2: mean over N.
// ---------------------------------------------------------------------------
__global__ void mean_kernel()
{
    int idx = blockIdx.x * blockDim.x + threadIdx.x;
    if (idx >= BATCH * MATELEMS) return;
    const float* p = g_logm + idx;
    float s = 0.f;
    #pragma unroll 4
    for (int i = 0; i < NMATS; ++i)
        s += p[(size_t)i * (BATCH * MATELEMS)];
    g_mean[idx] = s * (1.f / NMATS);
}

// ---------------------------------------------------------------------------
// Stage 3: expm via scaling-and-squaring Taylor (E = mean/16, degree-8
// Horner, 4 squarings). One 256-thread block per batch entry. Packed fma2.
// ---------------------------------------------------------------------------
__device__ __forceinline__ void mm_acc2(u64* __restrict__ acc2,
                                        const float* __restrict__ A,
                                        const float* __restrict__ Bm,
                                        int m, int nb)
{
    #pragma unroll
    for (int n = 0; n < 8; ++n) acc2[n] = 0ull;
    for (int j = 0; j < DIM; ++j) {
        float av = A[m * LDU + j];
        u64 avp = pk(av, av);
        const u64* brow = (const u64*)&Bm[j * LDU + nb];
        #pragma unroll
        for (int n = 0; n < 8; ++n) acc2[n] = fma2(avp, brow[n], acc2[n]);
    }
}

__global__ __launch_bounds__(256) void expm_kernel(float* __restrict__ out)
{
    __shared__ __align__(16) float E[DIM * LDU];
    __shared__ __align__(16) float P[DIM * LDU];
    const int b = blockIdx.x;
    const int tid = threadIdx.x;
    const int m  = tid >> 2;
    const int nb = (tid & 3) << 4;    // 0,16,32,48 — even, u64-aligned

    for (int idx = tid; idx < MATELEMS; idx += 256) {
        int r = idx >> 6, c = idx & 63;
        float e = g_mean[b * MATELEMS + idx] * (1.f / 16.f);
        E[r * LDU + c] = e;
        P[r * LDU + c] = e * 0.125f + (r == c ? 1.f : 0.f);
    }
    __syncthreads();

    for (int k = 7; k >= 1; --k) {
        u64 acc2[8];
        mm_acc2(acc2, E, P, m, nb);
        __syncthreads();
        float inv = 1.f / (float)k;
        #pragma unroll
        for (int n = 0; n < 8; ++n) {
            float lo, hi;
            upk(acc2[n], lo, hi);
            int c0 = nb + 2 * n;
            P[m * LDU + c0]     = lo * inv + ((m == c0)     ? 1.f : 0.f);
            P[m * LDU + c0 + 1] = hi * inv + ((m == c0 + 1) ? 1.f : 0.f);
        }
        __syncthreads();
    }

    for (int sq = 0; sq < 4; ++sq) {
        u64 acc2[8];
        mm_acc2(acc2, P, P, m, nb);
        __syncthreads();
        #pragma unroll
        for (int n = 0; n < 8; ++n) {
            float lo, hi;
            upk(acc2[n], lo, hi);
            P[m * LDU + nb + 2 * n]     = lo;
            P[m * LDU + nb + 2 * n + 1] = hi;
        }
        __syncthreads();
    }

    for (int idx = tid; idx < MATELEMS; idx += 256) {
        int r = idx >> 6, c = idx & 63;
        out[(size_t)b * MATELEMS + idx] = P[r * LDU + c];
    }
}

// ---------------------------------------------------------------------------
extern "C" void kernel_launch(void* const* d_in, const int* in_sizes, int n_in,
                              void* d_out, int out_size)
{
    (void)in_sizes; (void)n_in; (void)out_size;
    const float* X = (const float*)d_in[0];
    float* out = (float*)d_out;

    jacobi_log_kernel<<<TOTAL, 64>>>(X);
    mean_kernel<<<(BATCH * MATELEMS + 255) / 256, 256>>>();
    expm_kernel<<<BATCH, 256>>>(out);
}

// round 17
// speedup vs baseline: 1.0611x; 1.0041x over previous
#include <cuda_runtime.h>
#include <cuda_fp16.h>
#include <math.h>

#define NMATS 200
#define BATCH 64
#define DIM 64
#define TOTAL (NMATS * BATCH)      // 12800
#define MATELEMS (DIM * DIM)       // 4096
#define LDU 66                     // even padded stride: aligned LDS.64, conflict-free
#define NSWEEPS 8
#define FULLMASK 0xffffffffu

// fp16 scratch: logm values are bounded (|log lambda| <= ~2.4), and the mean
// over N=200 suppresses independent rounding to ~4e-5 rms — negligible vs the
// 4e-4 Jacobi convergence error. Halves stage-2 traffic (210 MB -> 105 MB).
__device__ __half g_logm[(size_t)TOTAL * MATELEMS];
__device__ float  g_mean[BATCH * MATELEMS];

// ---- packed f32x2 helpers (Blackwell) -------------------------------------
typedef unsigned long long u64;
__device__ __forceinline__ u64 pk(float lo, float hi) {
    u64 r; asm("mov.b64 %0,{%1,%2};" : "=l"(r) : "f"(lo), "f"(hi)); return r;
}
__device__ __forceinline__ void upk(u64 v, float& lo, float& hi) {
    asm("mov.b64 {%0,%1},%2;" : "=f"(lo), "=f"(hi) : "l"(v));
}
__device__ __forceinline__ u64 fma2(u64 a, u64 b, u64 c) {
    u64 d; asm("fma.rn.f32x2 %0,%1,%2,%3;" : "=l"(d) : "l"(a), "l"(b), "l"(c)); return d;
}
__device__ __forceinline__ u64 mul2(u64 a, u64 b) {
    u64 d; asm("mul.rn.f32x2 %0,%1,%2;" : "=l"(d) : "l"(a), "l"(b)); return d;
}
__device__ __forceinline__ u64 add2(u64 a, u64 b) {
    u64 d; asm("add.rn.f32x2 %0,%1,%2;" : "=l"(d) : "l"(a), "l"(b)); return d;
}
// Horizontal sum of two packed accumulators: 1 packed add + 1 scalar add.
__device__ __forceinline__ float hsum2(u64 v0, u64 v1) {
    u64 s = add2(v0, v1);
    float lo, hi; upk(s, lo, hi);
    return lo + hi;
}

// ---------------------------------------------------------------------------
// Stage 1: register-resident one-sided Jacobi, recursive-bisection schedule,
// branchless deferred-cosine rotations, incremental norms, packed f32x2 math.
// TWO warps per matrix (row-split): lane t of warp w owns rows [32w,32w+32)
// of columns (2t, 2t+1), stored as 16 packed row-pairs per column.
// Cross-warp dot reduction: parity-alternated smem + 1 barrier/round; the
// reduced value is bit-identical in both warps, so scalar state replicates.
// Native u64 shuffles (no explicit pack/unpack movs around SHFL).
// NO launch_bounds: natural allocation is the only spill-free point
// (any reg cap makes ptxas spill the column arrays — verified R7/R8/R13).
// Inner loop is byte-for-byte the R16 optimum; only the final store is fp16.
// ---------------------------------------------------------------------------
__global__ void jacobi_log_kernel(const float* __restrict__ X)
{
    __shared__ __align__(16) float U[DIM * LDU];   // reconstruction
    __shared__ float gcoef[DIM];
    __shared__ float red[2][64];        // cross-warp reduce (round parity)

    const int tid  = threadIdx.x;       // 0..63
    const int lane = tid & 31;
    const int w    = tid >> 5;          // row-half
    const size_t mat = blockIdx.x;
    const float* Xm = X + mat * (size_t)MATELEMS;

    // Load owned half-columns; repack AoS (a,b) pairs -> row-pair packing.
    u64 A[16], B[16];
    {
        const u64* X8 = (const u64*)Xm;   // {col 2lane, col 2lane+1} per row
        #pragma unroll
        for (int j = 0; j < 16; ++j) {
            u64 v0 = X8[(size_t)(32 * w + 2 * j)     * 32 + lane];
            u64 v1 = X8[(size_t)(32 * w + 2 * j + 1) * 32 + lane];
            float a0, b0, a1, b1;
            upk(v0, a0, b0); upk(v1, a1, b1);
            A[j] = pk(a0, a1); B[j] = pk(b0, b1);
        }
    }

    // Initial norms: packed partial per half, reduce across warps.
    float na, nb;
    {
        u64 p2 = 0ull, p3 = 0ull, q2 = 0ull, q3 = 0ull;
        #pragma unroll
        for (int j = 0; j < 16; j += 2) {
            p2 = fma2(A[j], A[j], p2);     p3 = fma2(A[j+1], A[j+1], p3);
            q2 = fma2(B[j], B[j], q2);     q3 = fma2(B[j+1], B[j+1], q3);
        }
        float pna = hsum2(p2, p3);
        float pnb = hsum2(q2, q3);
        red[0][tid] = pna;
        red[1][tid] = pnb;
        __syncthreads();
        na = pna + red[0][lane + 32 * (1 - w)];
        nb = pnb + red[1][lane + 32 * (1 - w)];
        __syncthreads();
    }
    float sa = 1.f, sb = 1.f, isa = 1.f, isb = 1.f;

    const int other = lane + 32 * (1 - w);
    int par = 0;

    for (int sweep = 0; sweep < NSWEEPS; ++sweep) {
        int g = 32;                      // lanes per group (2g columns/group)
        #pragma unroll
        for (int level = 0; level < 6; ++level) {
            const int gm1 = g - 1;
            const int rot_src = (lane & ~gm1) | ((lane + 1) & gm1);

            for (int r = 0; r < g; ++r) {
                // Packed partial cross dot (own row half), 2 chains.
                u64 d0 = 0ull, d1 = 0ull;
                #pragma unroll
                for (int j = 0; j < 16; j += 2) {
                    d0 = fma2(A[j],     B[j],     d0);
                    d1 = fma2(A[j + 1], B[j + 1], d1);
                }
                float pd = hsum2(d0, d1);

                // Cross-warp reduce (bit-identical in both warps).
                red[par][tid] = pd;
                __syncthreads();
                float s01 = pd + red[par][other];
                par ^= 1;

                float a01 = s01 * sa * sb;                // true off-diagonal

                // Branchless rotation, single-division tangent:
                // t = -2*a01 / copysign(|d| + sqrt(d^2 + 4*a01^2), d)
                float d = na - nb;
                float a01sq = a01 * a01;
                bool act = a01sq > (1e-14f * (na * nb));
                float w2 = sqrtf(fmaf(d, d, 4.f * a01sq));
                float tt = __fdividef(-2.f * a01,
                                      copysignf(fabsf(d) + w2, d));
                tt = act ? tt : 0.f;
                float opt2 = fmaf(tt, tt, 1.f);
                float c = rsqrtf(opt2);                   // 1 when tt=0
                float h = opt2 * c;                       // = 1/c
                float t1 = tt * sb * isa;                 // t*sb/sa (no div)
                float t2 = tt * sa * isb;                 // t*sa/sb (no div)
                na = fmaf(-tt, a01, na);                  // a00' = a00 - t*a01
                nb = fmaf( tt, a01, nb);                  // a11' = a11 + t*a01
                sa *= c; sb *= c; isa *= h; isb *= h;     // deferred cosine

                // Fused packed rotate + ring-rotate of b (native u64 shfl).
                u64 t1p = pk(-t1, -t1), t2p = pk(t2, t2);
                #pragma unroll
                for (int j = 0; j < 16; ++j) {
                    u64 x = A[j], y = B[j];
                    u64 xn = fma2(t1p, y, x);
                    u64 yn = fma2(t2p, x, y);
                    A[j] = xn;
                    B[j] = __shfl_sync(FULLMASK, yn, rot_src);
                }
                nb  = __shfl_sync(FULLMASK, nb,  rot_src);
                sb  = __shfl_sync(FULLMASK, sb,  rot_src);
                isb = __shfl_sync(FULLMASK, isb, rot_src);
            }

            // Redistribute: low half-lanes collect the a-set, high half b-set.
            if (g > 1) {
                const int half = g >> 1;
                const bool low = (lane & gm1) < half;
                const int partner = low ? (lane + half) : (lane - half);
                #pragma unroll
                for (int j = 0; j < 16; ++j) {
                    u64 send = low ? B[j] : A[j];
                    u64 recv = __shfl_sync(FULLMASK, send, partner);
                    if (low) B[j] = recv; else A[j] = recv;
                }
                float sn = low ? nb : na;
                float rn = __shfl_sync(FULLMASK, sn, partner);
                if (low) nb = rn; else na = rn;
                float ss = low ? sb : sa;
                float rs = __shfl_sync(FULLMASK, ss, partner);
                if (low) sb = rs; else sa = rs;
                float si = low ? isb : isa;
                float ri = __shfl_sync(FULLMASK, si, partner);
                if (low) isb = ri; else isa = ri;
            }
            g >>= 1;
        }

        // Renormalize stored columns once per sweep (packed).
        {
            u64 sap = pk(sa, sa), sbp = pk(sb, sb);
            #pragma unroll
            for (int j = 0; j < 16; ++j) {
                A[j] = mul2(A[j], sap);
                B[j] = mul2(B[j], sbp);
            }
        }
        sa = 1.f; sb = 1.f; isa = 1.f; isb = 1.f;
    }

    // Stash converged half-columns (aligned u64 stores).
    #pragma unroll
    for (int j = 0; j < 16; ++j) {
        *(u64*)&U[(2 * lane)     * LDU + 32 * w + 2 * j] = A[j];
        *(u64*)&U[(2 * lane + 1) * LDU + 32 * w + 2 * j] = B[j];
    }
    // Exact final norms -> spectral coefficients.
    {
        u64 p2 = 0ull, p3 = 0ull, q2 = 0ull, q3 = 0ull;
        #pragma unroll
        for (int j = 0; j < 16; j += 2) {
            p2 = fma2(A[j], A[j], p2);     p3 = fma2(A[j+1], A[j+1], p3);
            q2 = fma2(B[j], B[j], q2);     q3 = fma2(B[j+1], B[j+1], q3);
        }
        float pna = hsum2(p2, p3);
        float pnb = hsum2(q2, q3);
        red[0][tid] = pna;
        red[1][tid] = pnb;
        __syncthreads();
        if (w == 0) {
            float nna = pna + red[0][other];   // lambda^2
            float nnb = pnb + red[1][other];
            gcoef[2 * lane]     = 0.5f * logf(nna) / nna;
            gcoef[2 * lane + 1] = 0.5f * logf(nnb) / nnb;
        }
    }
    __syncthreads();

    // logm = sum_j g_j u_j u_j^T; thread handles row m = tid. Packed fma2,
    // fp16 stores (coalesced 2B across adjacent threads m).
    __half* outm = g_logm + mat * (size_t)MATELEMS;
    const int m = tid;
    for (int h2 = 0; h2 < 2; ++h2) {
        u64 acc2[16];
        #pragma unroll
        for (int n = 0; n < 16; ++n) acc2[n] = 0ull;
        for (int j = 0; j < DIM; ++j) {
            float aj = gcoef[j] * U[j * LDU + m];
            u64 ajp = pk(aj, aj);
            const u64* uj2 = (const u64*)&U[j * LDU + h2 * 32];
            #pragma unroll
            for (int n = 0; n < 16; ++n) acc2[n] = fma2(ajp, uj2[n], acc2[n]);
        }
        #pragma unroll
        for (int n = 0; n < 16; ++n) {
            float lo, hi;
            upk(acc2[n], lo, hi);
            outm[(size_t)(h2 * 32 + 2 * n)     * DIM + m] = __float2half_rn(lo);
            outm[(size_t)(h2 * 32 + 2 * n + 1) * DIM + m] = __float2half_rn(hi);
        }
    }
}

// ---------------------------------------------------------------------------
// Stage 2: mean over N. half2-vectorized: each thread sums one half2 lane
// (2 adjacent elements) over the N axis, writes float2.
// ---------------------------------------------------------------------------
__global__ void mean_kernel()
{
    int idx = blockIdx.x * blockDim.x + threadIdx.x;   // half2 index in (b,e)
    if (idx >= BATCH * MATELEMS / 2) return;
    const __half2* p = ((const __half2*)g_logm) + idx;
    float sx = 0.f, sy = 0.f;
    #pragma unroll 4
    for (int i = 0; i < NMATS; ++i) {
        float2 v = __half22float2(p[(size_t)i * (BATCH * MATELEMS / 2)]);
        sx += v.x; sy += v.y;
    }
    float2 o; o.x = sx * (1.f / NMATS); o.y = sy * (1.f / NMATS);
    ((float2*)g_mean)[idx] = o;
}

// ---------------------------------------------------------------------------
// Stage 3: expm via scaling-and-squaring Taylor (E = mean/16, degree-8
// Horner, 4 squarings). One 256-thread block per batch entry. Packed fma2.
// ---------------------------------------------------------------------------
__device__ __forceinline__ void mm_acc2(u64* __restrict__ acc2,
                                        const float* __restrict__ A,
                                        const float* __restrict__ Bm,
                                        int m, int nb)
{
    #pragma unroll
    for (int n = 0; n < 8; ++n) acc2[n] = 0ull;
    for (int j = 0; j < DIM; ++j) {
        float av = A[m * LDU + j];
        u64 avp = pk(av, av);
        const u64* brow = (const u64*)&Bm[j * LDU + nb];
        #pragma unroll
        for (int n = 0; n < 8; ++n) acc2[n] = fma2(avp, brow[n], acc2[n]);
    }
}

__global__ __launch_bounds__(256) void expm_kernel(float* __restrict__ out)
{
    __shared__ __align__(16) float E[DIM * LDU];
    __shared__ __align__(16) float P[DIM * LDU];
    const int b = blockIdx.x;
    const int tid = threadIdx.x;
    const int m  = tid >> 2;
    const int nb = (tid & 3) << 4;    // 0,16,32,48 — even, u64-aligned

    for (int idx = tid; idx < MATELEMS; idx += 256) {
        int r = idx >> 6, c = idx & 63;
        float e = g_mean[b * MATELEMS + idx] * (1.f / 16.f);
        E[r * LDU + c] = e;
        P[r * LDU + c] = e * 0.125f + (r == c ? 1.f : 0.f);
    }
    __syncthreads();

    for (int k = 7; k >= 1; --k) {
        u64 acc2[8];
        mm_acc2(acc2, E, P, m, nb);
        __syncthreads();
        float inv = 1.f / (float)k;
        #pragma unroll
        for (int n = 0; n < 8; ++n) {
            float lo, hi;
            upk(acc2[n], lo, hi);
            int c0 = nb + 2 * n;
            P[m * LDU + c0]     = lo * inv + ((m == c0)     ? 1.f : 0.f);
            P[m * LDU + c0 + 1] = hi * inv + ((m == c0 + 1) ? 1.f : 0.f);
        }
        __syncthreads();
    }

    for (int sq = 0; sq < 4; ++sq) {
        u64 acc2[8];
        mm_acc2(acc2, P, P, m, nb);
        __syncthreads();
        #pragma unroll
        for (int n = 0; n < 8; ++n) {
            float lo, hi;
            upk(acc2[n], lo, hi);
            P[m * LDU + nb + 2 * n]     = lo;
            P[m * LDU + nb + 2 * n + 1] = hi;
        }
        __syncthreads();
    }

    for (int idx = tid; idx < MATELEMS; idx += 256) {
        int r = idx >> 6, c = idx & 63;
        out[(size_t)b * MATELEMS + idx] = P[r * LDU + c];
    }
}

// ---------------------------------------------------------------------------
extern "C" void kernel_launch(void* const* d_in, const int* in_sizes, int n_in,
                              void* d_out, int out_size)
{
    (void)in_sizes; (void)n_in; (void)out_size;
    const float* X = (const float*)d_in[0];
    float* out = (float*)d_out;

    jacobi_log_kernel<<<TOTAL, 64>>>(X);
    mean_kernel<<<(BATCH * MATELEMS / 2 + 255) / 256, 256>>>();
    expm_kernel<<<BATCH, 256>>>(out);
}